// round 2
// baseline (speedup 1.0000x reference)
#include <cuda_runtime.h>
#include <math.h>

#define T_STEPS 1440
#define UNROLL 8
#define NGROUPS (T_STEPS / UNROLL)   // 180
#define BLOCK 128

__device__ __forceinline__ float bounded_sig(float raw, float lo, float hi) {
    // lo + (hi-lo) * sigmoid(raw)
    float s = 1.0f / (1.0f + expf(-raw));
    return lo + (hi - lo) * s;
}

__global__ void __launch_bounds__(BLOCK, 1) rc_scan_kernel(
    const float4* __restrict__ in,   // (B, T, 4) viewed as float4 rows
    float* __restrict__ out,         // (B, T)
    const float* __restrict__ rRi, const float* __restrict__ rRe,
    const float* __restrict__ rCi, const float* __restrict__ rCe,
    const float* __restrict__ rAi, const float* __restrict__ rAe,
    const float* __restrict__ rHg,
    int B)
{
    int b = blockIdx.x * BLOCK + threadIdx.x;
    if (b >= B) return;

    // --- parameters (broadcast scalar loads, L1/const-cached) ---
    float Ri = bounded_sig(rRi[0], 1e-4f, 0.2f);
    float Re = bounded_sig(rRe[0], 1e-4f, 0.2f);
    float Ci = bounded_sig(rCi[0], 1e5f,  1e8f);
    float Ce = bounded_sig(rCe[0], 1e5f,  1e8f);
    float Ai = bounded_sig(rAi[0], 0.0f,  0.2f);
    float Ae = bounded_sig(rAe[0], 0.0f,  0.2f);
    float Hg = bounded_sig(rHg[0], 1.0f,  2e4f);

    float invRi = 1.0f / Ri;
    float invRe = 1.0f / Re;
    float dci = 300.0f / Ci;     // DELTA_T / Ci
    float dce = 300.0f / Ce;     // DELTA_T / Ce
    // t_in'  = t_in  + k1*(t_env - t_in) + k2*solar + k3*hvac_u
    // t_env' = t_env + e1*(t_in - t_env) + e2*(t_out - t_env) + e3*solar
    float k1 = dci * invRi;
    float k2 = dci * Ai;
    float k3 = -dci * Hg;        // MODE_COOL => cooling_sign = -1
    float e1 = dce * invRi;
    float e2 = dce * invRe;
    float e3 = dce * Ae;

    const float4* row  = in + (size_t)b * T_STEPS;
    float4*       orow = reinterpret_cast<float4*>(out) + (size_t)b * (T_STEPS / 4);

    // --- software pipeline: double-buffered groups of UNROLL timesteps ---
    float4 cur[UNROLL], nxt[UNROLL];
    #pragma unroll
    for (int j = 0; j < UNROLL; j++) cur[j] = row[j];

    float t_in  = cur[0].x;
    float t_env = 0.5f * (cur[0].x + cur[0].y);

    #pragma unroll 1
    for (int g = 0; g < NGROUPS - 1; g++) {
        // prefetch next group (8 independent LDG.128 in flight during compute)
        const float4* nrow = row + (size_t)(g + 1) * UNROLL;
        #pragma unroll
        for (int j = 0; j < UNROLL; j++) nxt[j] = nrow[j];

        float outs[UNROLL];
        #pragma unroll
        for (int j = 0; j < UNROLL; j++) {
            float t_out = cur[j].y;
            float hv    = cur[j].z;
            float sol   = cur[j].w;
            float p    = fmaf(k2, sol, k3 * hv);                  // indep of carry
            float nin  = fmaf(k1, t_env - t_in, t_in + p);
            float q    = fmaf(e3, sol, t_env);
            float nenv = fmaf(e1, t_in - t_env, fmaf(e2, t_out - t_env, q));
            t_in  = nin;
            t_env = nenv;
            outs[j] = nin;
        }
        orow[g * 2 + 0] = make_float4(outs[0], outs[1], outs[2], outs[3]);
        orow[g * 2 + 1] = make_float4(outs[4], outs[5], outs[6], outs[7]);

        #pragma unroll
        for (int j = 0; j < UNROLL; j++) cur[j] = nxt[j];
    }

    // --- peeled last group (no prefetch past end) ---
    {
        int g = NGROUPS - 1;
        float outs[UNROLL];
        #pragma unroll
        for (int j = 0; j < UNROLL; j++) {
            float t_out = cur[j].y;
            float hv    = cur[j].z;
            float sol   = cur[j].w;
            float p    = fmaf(k2, sol, k3 * hv);
            float nin  = fmaf(k1, t_env - t_in, t_in + p);
            float q    = fmaf(e3, sol, t_env);
            float nenv = fmaf(e1, t_in - t_env, fmaf(e2, t_out - t_env, q));
            t_in  = nin;
            t_env = nenv;
            outs[j] = nin;
        }
        orow[g * 2 + 0] = make_float4(outs[0], outs[1], outs[2], outs[3]);
        orow[g * 2 + 1] = make_float4(outs[4], outs[5], outs[6], outs[7]);
    }
}

extern "C" void kernel_launch(void* const* d_in, const int* in_sizes, int n_in,
                              void* d_out, int out_size) {
    const float4* in = (const float4*)d_in[0];
    const float* rRi = (const float*)d_in[1];
    const float* rRe = (const float*)d_in[2];
    const float* rCi = (const float*)d_in[3];
    const float* rCe = (const float*)d_in[4];
    const float* rAi = (const float*)d_in[5];
    const float* rAe = (const float*)d_in[6];
    const float* rHg = (const float*)d_in[7];
    float* out = (float*)d_out;

    int B = in_sizes[0] / (T_STEPS * 4);
    int grid = (B + BLOCK - 1) / BLOCK;
    rc_scan_kernel<<<grid, BLOCK>>>(in, out, rRi, rRe, rCi, rCe, rAi, rAe, rHg, B);
}

// round 3
// speedup vs baseline: 1.3326x; 1.3326x over previous
#include <cuda_runtime.h>
#include <math.h>

#define T_STEPS 1440
#define SEG_LEN 32
#define NSEG    45           // 1440 / 32
#define B_MAX   16384
#define K1_WARPS 4
#define K3_THREADS 256

// Scratch: per-(segment,building) forcing accumulation and segment start states.
// Layout [s][b] (float2) so warp-lane access over b is coalesced.
__device__ float2 g_d [NSEG * B_MAX];
__device__ float2 g_xs[NSEG * B_MAX];

struct Coefs { float k1, k2, k3, e1, e2, e3; };

__device__ __forceinline__ float bsig(float raw, float lo, float hi) {
    return lo + (hi - lo) / (1.0f + expf(-raw));
}

__device__ __forceinline__ Coefs get_coefs(
    const float* rRi, const float* rRe, const float* rCi, const float* rCe,
    const float* rAi, const float* rAe, const float* rHg)
{
    float Ri = bsig(rRi[0], 1e-4f, 0.2f);
    float Re = bsig(rRe[0], 1e-4f, 0.2f);
    float Ci = bsig(rCi[0], 1e5f,  1e8f);
    float Ce = bsig(rCe[0], 1e5f,  1e8f);
    float Ai = bsig(rAi[0], 0.0f,  0.2f);
    float Ae = bsig(rAe[0], 0.0f,  0.2f);
    float Hg = bsig(rHg[0], 1.0f,  2e4f);
    float dci = 300.0f / Ci;
    float dce = 300.0f / Ce;
    Coefs c;
    c.k1 = dci / Ri;  c.k2 = dci * Ai;  c.k3 = -dci * Hg;  // MODE_COOL
    c.e1 = dce / Ri;  c.e2 = dce / Re;  c.e3 = dce * Ae;
    return c;
}

// ---------------------------------------------------------------------------
// K1: per-segment zero-init partial scan. Warp = 32 buildings x 1 segment.
// Coalesced tile loads (4 lines / LDG.128) via smem transpose; coalesced
// 128B-row output flush. Writes partial outs + segment forcing d.
// ---------------------------------------------------------------------------
__global__ void __launch_bounds__(32 * K1_WARPS) k1_partial(
    const float4* __restrict__ in, float* __restrict__ out,
    const float* __restrict__ rRi, const float* __restrict__ rRe,
    const float* __restrict__ rCi, const float* __restrict__ rCe,
    const float* __restrict__ rAi, const float* __restrict__ rAe,
    const float* __restrict__ rHg, int B)
{
    __shared__ float4 tile [K1_WARPS][32][9];   // [warp][building][tstep] (+pad)
    __shared__ float  otile[K1_WARPS][32][33];  // [warp][building][tstep] (+pad)

    int w    = threadIdx.x >> 5;
    int lane = threadIdx.x & 31;
    int s    = blockIdx.y * K1_WARPS + w;
    if (s >= NSEG) return;                       // warp-uniform exit; no block barriers used
    int b0 = blockIdx.x * 32;

    Coefs c = get_coefs(rRi, rRe, rCi, rCe, rAi, rAe, rHg);

    int t0 = s * SEG_LEN;
    const float4* base = in + (size_t)b0 * T_STEPS + t0;

    int jr = lane & 7;     // col within 8-step chunk (load phase)
    int rr = lane >> 3;    // row group (load phase): 8 lanes per row

    float pin = 0.0f, penv = 0.0f;               // zero-init partial state

    #pragma unroll
    for (int ch = 0; ch < 4; ch++) {             // 4 chunks x 8 steps = 32
        // cooperative coalesced load: inst i covers 4 rows, 1 line per row
        #pragma unroll
        for (int i = 0; i < 8; i++) {
            int r = i * 4 + rr;
            tile[w][r][jr] = base[(size_t)r * T_STEPS + ch * 8 + jr];
        }
        __syncwarp();
        #pragma unroll
        for (int j = 0; j < 8; j++) {
            float4 f = tile[w][lane][j];         // lane = building
            float t_out = f.y, hv = f.z, sol = f.w;
            float p    = fmaf(c.k2, sol, c.k3 * hv);
            float nin  = fmaf(c.k1, penv - pin, pin + p);
            float q    = fmaf(c.e3, sol, penv);
            float nenv = fmaf(c.e1, pin - penv, fmaf(c.e2, t_out - penv, q));
            pin = nin; penv = nenv;
            otile[w][lane][ch * 8 + j] = nin;
        }
        __syncwarp();
    }

    // segment forcing accumulation (coalesced float2 over b)
    g_d[s * B + b0 + lane] = make_float2(pin, penv);

    // flush partial outputs: one 128B row-chunk per instruction
    float* obase = out + (size_t)b0 * T_STEPS + t0;
    #pragma unroll
    for (int i = 0; i < 32; i++) {
        obase[(size_t)i * T_STEPS + lane] = otile[w][i][lane];
    }
}

// ---------------------------------------------------------------------------
// K2: sequential combine over segments. M = A^32 via 5 squarings.
// x_start[0] = (t_in0, 0.5*(t_in0+t_out0)); x_start[s+1] = M*x_start[s] + d[s].
// ---------------------------------------------------------------------------
__global__ void k2_combine(
    const float4* __restrict__ in,
    const float* __restrict__ rRi, const float* __restrict__ rRe,
    const float* __restrict__ rCi, const float* __restrict__ rCe,
    const float* __restrict__ rAi, const float* __restrict__ rAe,
    const float* __restrict__ rHg, int B)
{
    int b = blockIdx.x * blockDim.x + threadIdx.x;
    if (b >= B) return;

    Coefs c = get_coefs(rRi, rRe, rCi, rCe, rAi, rAe, rHg);
    float m00 = 1.0f - c.k1, m01 = c.k1;
    float m10 = c.e1,        m11 = 1.0f - c.e1 - c.e2;
    #pragma unroll
    for (int i = 0; i < 5; i++) {                // A -> A^32
        float tr  = m00 + m11;
        float n00 = fmaf(m00, m00, m01 * m10);
        float n11 = fmaf(m11, m11, m01 * m10);
        float n01 = m01 * tr;
        float n10 = m10 * tr;
        m00 = n00; m01 = n01; m10 = n10; m11 = n11;
    }

    float4 f0 = in[(size_t)b * T_STEPS];
    float xi = f0.x;
    float xe = 0.5f * (f0.x + f0.y);

    float2 dn = g_d[b];
    #pragma unroll 1
    for (int s = 0; s < NSEG; s++) {
        float2 dc = dn;
        if (s + 1 < NSEG) dn = g_d[(s + 1) * B + b];   // prefetch next
        g_xs[s * B + b] = make_float2(xi, xe);
        float nxi = fmaf(m00, xi, fmaf(m01, xe, dc.x));
        float nxe = fmaf(m10, xi, fmaf(m11, xe, dc.y));
        xi = nxi; xe = nxe;
    }
}

// ---------------------------------------------------------------------------
// K3: correction pass. out[b, s*32+j] += row0(A^{j+1}) . x_start[s][b].
// Block = 32 buildings x full time axis; thread owns one float4 t-chunk per
// segment -> fully coalesced float4 RMW stream.
// ---------------------------------------------------------------------------
__global__ void __launch_bounds__(K3_THREADS) k3_correct(
    float* __restrict__ out,
    const float* __restrict__ rRi, const float* __restrict__ rRe,
    const float* __restrict__ rCi, const float* __restrict__ rCe,
    const float* __restrict__ rAi, const float* __restrict__ rAe,
    const float* __restrict__ rHg, int B)
{
    int b0 = blockIdx.x * 32;
    int jc = threadIdx.x & 7;    // float4 chunk within segment (t_local = jc*4..+3)
    int r  = threadIdx.x >> 3;   // building row 0..31

    Coefs c = get_coefs(rRi, rRe, rCi, rCe, rAi, rAe, rHg);
    float a00 = 1.0f - c.k1, a01 = c.k1;
    float a10 = c.e1,        a11 = 1.0f - c.e1 - c.e2;

    // (al, be) = row0(A^{j+1}); capture j = jc*4 .. jc*4+3
    float al = a00, be = a01;
    float4 A4, B4;
    int jbase = jc * 4;
    #pragma unroll
    for (int j = 0; j < SEG_LEN; j++) {
        if (j == jbase    ) { A4.x = al; B4.x = be; }
        if (j == jbase + 1) { A4.y = al; B4.y = be; }
        if (j == jbase + 2) { A4.z = al; B4.z = be; }
        if (j == jbase + 3) { A4.w = al; B4.w = be; }
        float nal = fmaf(al, a00, be * a10);
        float nbe = fmaf(al, a01, be * a11);
        al = nal; be = nbe;
    }

    float4* orow = reinterpret_cast<float4*>(out + (size_t)(b0 + r) * T_STEPS);
    #pragma unroll 5
    for (int s = 0; s < NSEG; s++) {
        float2 xs = g_xs[s * B + b0 + r];
        float4 o  = orow[s * 8 + jc];
        o.x = fmaf(A4.x, xs.x, fmaf(B4.x, xs.y, o.x));
        o.y = fmaf(A4.y, xs.x, fmaf(B4.y, xs.y, o.y));
        o.z = fmaf(A4.z, xs.x, fmaf(B4.z, xs.y, o.z));
        o.w = fmaf(A4.w, xs.x, fmaf(B4.w, xs.y, o.w));
        orow[s * 8 + jc] = o;
    }
}

// ---------------------------------------------------------------------------
extern "C" void kernel_launch(void* const* d_in, const int* in_sizes, int n_in,
                              void* d_out, int out_size) {
    const float4* in  = (const float4*)d_in[0];
    const float* rRi = (const float*)d_in[1];
    const float* rRe = (const float*)d_in[2];
    const float* rCi = (const float*)d_in[3];
    const float* rCe = (const float*)d_in[4];
    const float* rAi = (const float*)d_in[5];
    const float* rAe = (const float*)d_in[6];
    const float* rHg = (const float*)d_in[7];
    float* out = (float*)d_out;

    int B = in_sizes[0] / (T_STEPS * 4);   // 16384

    dim3 g1(B / 32, (NSEG + K1_WARPS - 1) / K1_WARPS);
    k1_partial<<<g1, 32 * K1_WARPS>>>(in, out, rRi, rRe, rCi, rCe, rAi, rAe, rHg, B);

    k2_combine<<<(B + 127) / 128, 128>>>(in, rRi, rRe, rCi, rCe, rAi, rAe, rHg, B);

    k3_correct<<<B / 32, K3_THREADS>>>(out, rRi, rRe, rCi, rCe, rAi, rAe, rHg, B);
}

// round 4
// speedup vs baseline: 2.2178x; 1.6642x over previous
#include <cuda_runtime.h>
#include <math.h>

#define T_STEPS 1440
#define SEG_LEN 32
#define NSEG    45           // 1440 / 32
#define B_MAX   16384

// Decoupled-lookback state. Separate partial/inclusive payload arrays so a
// flag upgrade (1 -> 2) can never produce a torn payload read (CUB pattern).
__device__ float2 g_part[NSEG * B_MAX];
__device__ float2 g_incl[NSEG * B_MAX];
__device__ int    g_flag[NSEG * B_MAX];

struct Coefs { float k1, k2, k3, e1, e2, e3; };

__device__ __forceinline__ float bsig(float raw, float lo, float hi) {
    return lo + (hi - lo) / (1.0f + expf(-raw));
}

__device__ __forceinline__ Coefs get_coefs(
    const float* rRi, const float* rRe, const float* rCi, const float* rCe,
    const float* rAi, const float* rAe, const float* rHg)
{
    float Ri = bsig(rRi[0], 1e-4f, 0.2f);
    float Re = bsig(rRe[0], 1e-4f, 0.2f);
    float Ci = bsig(rCi[0], 1e5f,  1e8f);
    float Ce = bsig(rCe[0], 1e5f,  1e8f);
    float Ai = bsig(rAi[0], 0.0f,  0.2f);
    float Ae = bsig(rAe[0], 0.0f,  0.2f);
    float Hg = bsig(rHg[0], 1.0f,  2e4f);
    float dci = 300.0f / Ci;
    float dce = 300.0f / Ce;
    Coefs c;
    c.k1 = dci / Ri;  c.k2 = dci * Ai;  c.k3 = -dci * Hg;  // MODE_COOL
    c.e1 = dce / Ri;  c.e2 = dce / Re;  c.e3 = dce * Ae;
    return c;
}

// One warp-block per (32-building tile, segment). Local zero-init scan with
// outputs in registers; decoupled lookback for the true segment start state;
// in-register affine correction; single coalesced output write.
__global__ void __launch_bounds__(32) rc_lookback(
    const float4* __restrict__ in, float* __restrict__ out,
    const float* __restrict__ rRi, const float* __restrict__ rRe,
    const float* __restrict__ rCi, const float* __restrict__ rCe,
    const float* __restrict__ rAi, const float* __restrict__ rAe,
    const float* __restrict__ rHg, int B)
{
    // union buffer: input tile (32 rows x 9 float4, padded) then output stage
    __shared__ __align__(16) char sbuf[32 * 9 * 16];
    float4* tile = reinterpret_cast<float4*>(sbuf);

    int lane = threadIdx.x;
    int s    = blockIdx.y;
    int b0   = blockIdx.x * 32;
    int b    = b0 + lane;            // this lane's building

    Coefs c = get_coefs(rRi, rRe, rCi, rCe, rAi, rAe, rHg);
    float a00 = 1.0f - c.k1, a01 = c.k1;
    float a10 = c.e1,        a11 = 1.0f - c.e1 - c.e2;

    const float4* base = in + (size_t)b0 * T_STEPS + s * SEG_LEN;
    int jr = lane & 7;     // t-col within 8-step chunk (load phase)
    int rr = lane >> 3;    // row-group (load phase)

    float outs[SEG_LEN];
    float pin = 0.0f, penv = 0.0f;
    bool first = (s == 0);

    #pragma unroll
    for (int ch = 0; ch < 4; ch++) {
        #pragma unroll
        for (int i = 0; i < 8; i++) {          // coalesced: 1 line per row
            int r = i * 4 + rr;
            tile[r * 9 + jr] = base[(size_t)r * T_STEPS + ch * 8 + jr];
        }
        __syncwarp();
        if (ch == 0 && first) {                // true initial condition
            float4 f0 = tile[lane * 9 + 0];
            pin  = f0.x;
            penv = 0.5f * (f0.x + f0.y);
        }
        #pragma unroll
        for (int j = 0; j < 8; j++) {
            float4 f = tile[lane * 9 + j];     // conflict-free (36-word rows)
            float t_out = f.y, hv = f.z, sol = f.w;
            float p    = fmaf(c.k2, sol, c.k3 * hv);
            float nin  = fmaf(c.k1, penv - pin, pin + p);
            float q    = fmaf(c.e3, sol, penv);
            float nenv = fmaf(c.e1, pin - penv, fmaf(c.e2, t_out - penv, q));
            pin = nin; penv = nenv;
            outs[ch * 8 + j] = nin;
        }
        __syncwarp();
    }

    int idx = s * B + b;
    if (first) {
        // segment 0 ran with the true init: publish inclusive directly
        g_incl[idx] = make_float2(pin, penv);
        __threadfence();
        *(volatile int*)&g_flag[idx] = 2;
    } else {
        g_part[idx] = make_float2(pin, penv);
        __threadfence();
        *(volatile int*)&g_flag[idx] = 1;

        // M = A^32 via 5 squarings
        float m00 = a00, m01 = a01, m10 = a10, m11 = a11;
        #pragma unroll
        for (int i = 0; i < 5; i++) {
            float tr  = m00 + m11;
            float n00 = fmaf(m00, m00, m01 * m10);
            float n11 = fmaf(m11, m11, m01 * m10);
            float n01 = m01 * tr;
            float n10 = m10 * tr;
            m00 = n00; m01 = n01; m10 = n10; m11 = n11;
        }

        // lookback: x_start = d_{s-1} + M d_{s-2} + ... + M^{s-1-i} incl_i
        float xi = 0.0f, xe = 0.0f;
        float p00 = 1.0f, p01 = 0.0f, p10 = 0.0f, p11 = 1.0f;
        for (int i = s - 1; i >= 0; --i) {
            int pidx = i * B + b;
            int f;
            while ((f = *(volatile int*)&g_flag[pidx]) == 0) { __nanosleep(40); }
            __threadfence();
            const float* vp = (f == 2) ? (const float*)&g_incl[pidx]
                                       : (const float*)&g_part[pidx];
            float vx = *(volatile const float*)(vp + 0);
            float vy = *(volatile const float*)(vp + 1);
            xi = fmaf(p00, vx, fmaf(p01, vy, xi));
            xe = fmaf(p10, vx, fmaf(p11, vy, xe));
            if (f == 2) break;
            float q00 = fmaf(p00, m00, p01 * m10), q01 = fmaf(p00, m01, p01 * m11);
            float q10 = fmaf(p10, m00, p11 * m10), q11 = fmaf(p10, m01, p11 * m11);
            p00 = q00; p01 = q01; p10 = q10; p11 = q11;
        }

        // publish inclusive ASAP to unblock successors
        float ix = fmaf(m00, xi, fmaf(m01, xe, pin));
        float ie = fmaf(m10, xi, fmaf(m11, xe, penv));
        g_incl[idx] = make_float2(ix, ie);
        __threadfence();
        *(volatile int*)&g_flag[idx] = 2;

        // in-register correction: outs[j] += row0(A^{j+1}) . x_start
        float al = a00, be = a01;
        #pragma unroll
        for (int j = 0; j < SEG_LEN; j++) {
            outs[j] = fmaf(al, xi, fmaf(be, xe, outs[j]));
            float nal = fmaf(al, a00, be * a10);
            float nbe = fmaf(al, a01, be * a11);
            al = nal; be = nbe;
        }
    }

    // transpose through smem (reusing the tile buffer), coalesced 128B rows
    __syncwarp();
    float* ot = reinterpret_cast<float*>(sbuf);
    #pragma unroll
    for (int j = 0; j < SEG_LEN; j++) ot[lane * 33 + j] = outs[j];  // conflict-free
    __syncwarp();
    float* obase = out + (size_t)b0 * T_STEPS + s * SEG_LEN;
    #pragma unroll
    for (int r = 0; r < 32; r++)
        obase[(size_t)r * T_STEPS + lane] = ot[r * 33 + lane];
}

// ---------------------------------------------------------------------------
extern "C" void kernel_launch(void* const* d_in, const int* in_sizes, int n_in,
                              void* d_out, int out_size) {
    const float4* in  = (const float4*)d_in[0];
    const float* rRi = (const float*)d_in[1];
    const float* rRe = (const float*)d_in[2];
    const float* rCi = (const float*)d_in[3];
    const float* rCe = (const float*)d_in[4];
    const float* rAi = (const float*)d_in[5];
    const float* rAe = (const float*)d_in[6];
    const float* rHg = (const float*)d_in[7];
    float* out = (float*)d_out;

    int B = in_sizes[0] / (T_STEPS * 4);   // 16384

    // reset lookback flags (graph-capturable memset node; no allocation)
    void* flag_ptr = nullptr;
    cudaGetSymbolAddress(&flag_ptr, g_flag);
    cudaMemsetAsync(flag_ptr, 0, (size_t)NSEG * B_MAX * sizeof(int), 0);

    dim3 grid(B / 32, NSEG);
    rc_lookback<<<grid, 32>>>(in, out, rRi, rRe, rCi, rCe, rAi, rAe, rHg, B);
}